// round 4
// baseline (speedup 1.0000x reference)
#include <cuda_runtime.h>
#include <math.h>

// ---------------- problem constants ----------------
#define B_    2
#define H_    112
#define W_    112
#define C_    192
#define LTOK  12544          // H*W
#define MROWS 25088          // B*L
#define CB    96             // C/2
#define NHB   4
#define HD    24
#define HID   768            // 4*C
#define NREL  2899           // (2*Hsp-1)*(2*Wsp-1) for both branches
#define NWIN  784            // tokens per window (112*7)

// ---------------- scratch (static device allocations) ----------------
__device__ float g_xn [MROWS * C_];
__device__ float g_qkv[MROWS * 3 * C_];
__device__ float g_att[MROWS * C_];
__device__ float g_x2 [MROWS * C_];
__device__ float g_y  [MROWS * C_];
__device__ float g_h1 [MROWS * HID];
__device__ float g_pos[2 * NREL * NHB];

// ---------------- LayerNorm: one warp per row of 192 ----------------
__global__ __launch_bounds__(256) void ln_kernel(const float* __restrict__ x,
                                                 const float* __restrict__ w,
                                                 const float* __restrict__ b,
                                                 float* __restrict__ y)
{
    int row  = blockIdx.x * 8 + (threadIdx.x >> 5);
    int lane = threadIdx.x & 31;
    const float* xr = x + (size_t)row * C_;
    float v[6];
    float s = 0.f;
#pragma unroll
    for (int i = 0; i < 6; i++) { v[i] = xr[lane + 32 * i]; s += v[i]; }
#pragma unroll
    for (int o = 16; o; o >>= 1) s += __shfl_xor_sync(0xffffffffu, s, o);
    float mu = s * (1.f / 192.f);
    float var = 0.f;
#pragma unroll
    for (int i = 0; i < 6; i++) { float d = v[i] - mu; var = fmaf(d, d, var); }
#pragma unroll
    for (int o = 16; o; o >>= 1) var += __shfl_xor_sync(0xffffffffu, var, o);
    float inv = rsqrtf(var * (1.f / 192.f) + 1e-5f);
    float* yr = y + (size_t)row * C_;
#pragma unroll
    for (int i = 0; i < 6; i++) {
        int c = lane + 32 * i;
        yr[c] = (v[i] - mu) * inv * w[c] + b[c];
    }
}

// ---------------- dynamic position-bias MLP (tiny) ----------------
__device__ __forceinline__ void ln6_relu(const float* p, float* q,
                                         const float* lw, const float* lb)
{
    float mu = 0.f;
#pragma unroll
    for (int d = 0; d < 6; d++) mu += p[d];
    mu *= (1.f / 6.f);
    float var = 0.f;
#pragma unroll
    for (int d = 0; d < 6; d++) { float dd = p[d] - mu; var = fmaf(dd, dd, var); }
    var *= (1.f / 6.f);
    float inv = rsqrtf(var + 1e-5f);
#pragma unroll
    for (int d = 0; d < 6; d++) {
        float t = (p[d] - mu) * inv * lw[d] + lb[d];
        q[d] = fmaxf(t, 0.f);
    }
}

__global__ void pos_kernel(const float* __restrict__ pw,  const float* __restrict__ pb,
                           const float* __restrict__ l1w, const float* __restrict__ l1b,
                           const float* __restrict__ f1w, const float* __restrict__ f1b,
                           const float* __restrict__ l2w, const float* __restrict__ l2b,
                           const float* __restrict__ f2w, const float* __restrict__ f2b,
                           const float* __restrict__ l3w, const float* __restrict__ l3b,
                           const float* __restrict__ f3w, const float* __restrict__ f3b,
                           float* __restrict__ pos_tab)
{
    int br = blockIdx.y;
    int r  = blockIdx.x * 256 + threadIdx.x;
    if (r >= NREL) return;
    int Hsp = br ? 7 : 112;
    int Wsp = br ? 112 : 7;
    int W2  = 2 * Wsp - 1;
    int i = r / W2, j = r - i * W2;
    float g0 = (float)(i - (Hsp - 1));
    float g1 = (float)(j - (Wsp - 1));
    float p[6], q[6];
#pragma unroll
    for (int d = 0; d < 6; d++)
        p[d] = g0 * pw[br * 12 + 2 * d] + g1 * pw[br * 12 + 2 * d + 1] + pb[br * 6 + d];
    ln6_relu(p, q, l1w + br * 6, l1b + br * 6);
#pragma unroll
    for (int d = 0; d < 6; d++) {
        float acc = f1b[br * 6 + d];
#pragma unroll
        for (int e = 0; e < 6; e++) acc = fmaf(q[e], f1w[br * 36 + d * 6 + e], acc);
        p[d] = acc;
    }
    ln6_relu(p, q, l2w + br * 6, l2b + br * 6);
#pragma unroll
    for (int d = 0; d < 6; d++) {
        float acc = f2b[br * 6 + d];
#pragma unroll
        for (int e = 0; e < 6; e++) acc = fmaf(q[e], f2w[br * 36 + d * 6 + e], acc);
        p[d] = acc;
    }
    ln6_relu(p, q, l3w + br * 6, l3b + br * 6);
#pragma unroll
    for (int hh = 0; hh < 4; hh++) {
        float acc = f3b[br * 4 + hh];
#pragma unroll
        for (int e = 0; e < 6; e++) acc = fmaf(q[e], f3w[br * 24 + hh * 6 + e], acc);
        pos_tab[(br * NREL + r) * 4 + hh] = acc;
    }
}

// ---------------- fused window attention ----------------
// one block per (branch via template, batch, window, head); K,V + pos table in smem
template <int BR>
__global__ __launch_bounds__(512, 1) void attn_kernel(const float* __restrict__ qkv,
                                                      const float* __restrict__ pos_tab,
                                                      float* __restrict__ outp)
{
    constexpr int Hsp = (BR == 0) ? 112 : 7;
    constexpr int Wsp = (BR == 0) ? 7 : 112;
    constexpr int W2  = 2 * Wsp - 1;
    constexpr int P   = 785;               // pitch (gcd(785%32,32)=1 -> conflict-free transposed loads)
    extern __shared__ float sm[];
    float* Ks     = sm;                    // [24][785]
    float* Vs     = sm + 24 * P;           // [24][785]
    float* pos_sm = sm + 48 * P;           // [2899*4]

    int bi = blockIdx.x;
    int h = bi & 3, w = (bi >> 2) & 15, b = (bi >> 6) & 1;
    int tid = threadIdx.x, lane = tid & 31, wid = tid >> 5;

    for (int e = tid; e < NREL * 4; e += 512)
        pos_sm[e] = pos_tab[BR * NREL * 4 + e];

    const int kbase = b * LTOK * 576 + 192 + BR * CB + h * HD;
    const int vbase = kbase + 192;
    for (int e = tid; e < NWIN * HD; e += 512) {
        int j = e / HD, d = e - j * HD;
        int ih = j / Wsp, iw = j - ih * Wsp;
        int l = (BR == 0) ? (ih * W_ + w * 7 + iw) : ((w * 7 + ih) * W_ + iw);
        Ks[d * P + j] = qkv[kbase + l * 576 + d];
        Vs[d * P + j] = qkv[vbase + l * 576 + d];
    }
    __syncthreads();

    const float scale = 0.20412414523193154f;   // 24^-0.5
    const int qbase = b * LTOK * 576 + BR * CB + h * HD;
    const int obase = b * LTOK * C_  + BR * CB + h * HD;

    for (int pr = wid; pr < NWIN / 2; pr += 16) {
        int r0 = 2 * pr, r1 = r0 + 1;
        int ih0 = r0 / Wsp, iw0 = r0 - ih0 * Wsp;
        int ih1 = r1 / Wsp, iw1 = r1 - ih1 * Wsp;
        int l0 = (BR == 0) ? (ih0 * W_ + w * 7 + iw0) : ((w * 7 + ih0) * W_ + iw0);
        int l1 = (BR == 0) ? (ih1 * W_ + w * 7 + iw1) : ((w * 7 + ih1) * W_ + iw1);

        float q0 = 0.f, q1 = 0.f;
        if (lane < HD) {
            q0 = qkv[qbase + l0 * 576 + lane];
            q1 = qkv[qbase + l1 * 576 + lane];
        }
        float s0[25], s1[25];
#pragma unroll
        for (int t = 0; t < 25; t++) { s0[t] = 0.f; s1[t] = 0.f; }
#pragma unroll
        for (int d = 0; d < HD; d++) {
            float qa = __shfl_sync(0xffffffffu, q0, d);
            float qb = __shfl_sync(0xffffffffu, q1, d);
            const float* kd = Ks + d * P + lane;
#pragma unroll
            for (int t = 0; t < 25; t++) {
                float kv = kd[32 * t];        // OOB lanes read finite smem garbage; masked below
                s0[t] = fmaf(qa, kv, s0[t]);
                s1[t] = fmaf(qb, kv, s1[t]);
            }
        }
        // scale + bias + row max
        float m0 = -1e30f, m1 = -1e30f;
#pragma unroll
        for (int t = 0; t < 25; t++) {
            int j = lane + 32 * t;
            if (j < NWIN) {
                int jh = j / Wsp, jw = j - jh * Wsp;
                int i0 = ((ih0 - jh + Hsp - 1) * W2 + (iw0 - jw + Wsp - 1)) * 4 + h;
                int i1 = ((ih1 - jh + Hsp - 1) * W2 + (iw1 - jw + Wsp - 1)) * 4 + h;
                s0[t] = fmaf(s0[t], scale, pos_sm[i0]);
                s1[t] = fmaf(s1[t], scale, pos_sm[i1]);
            } else { s0[t] = -1e30f; s1[t] = -1e30f; }
            m0 = fmaxf(m0, s0[t]);
            m1 = fmaxf(m1, s1[t]);
        }
#pragma unroll
        for (int o = 16; o; o >>= 1) {
            m0 = fmaxf(m0, __shfl_xor_sync(0xffffffffu, m0, o));
            m1 = fmaxf(m1, __shfl_xor_sync(0xffffffffu, m1, o));
        }
        float ls0 = 0.f, ls1 = 0.f;
#pragma unroll
        for (int t = 0; t < 25; t++) {
            s0[t] = __expf(s0[t] - m0);   // invalid lanes -> exp(-huge) == 0
            s1[t] = __expf(s1[t] - m1);
            ls0 += s0[t]; ls1 += s1[t];
        }
#pragma unroll
        for (int o = 16; o; o >>= 1) {
            ls0 += __shfl_xor_sync(0xffffffffu, ls0, o);
            ls1 += __shfl_xor_sync(0xffffffffu, ls1, o);
        }
        float inv0 = 1.f / ls0, inv1 = 1.f / ls1;
        // A @ V
#pragma unroll
        for (int d = 0; d < HD; d++) {
            const float* vd = Vs + d * P + lane;
            float a0 = 0.f, a1 = 0.f;
#pragma unroll
            for (int t = 0; t < 25; t++) {
                float vv = vd[32 * t];
                a0 = fmaf(s0[t], vv, a0);
                a1 = fmaf(s1[t], vv, a1);
            }
#pragma unroll
            for (int o = 16; o; o >>= 1) {
                a0 += __shfl_xor_sync(0xffffffffu, a0, o);
                a1 += __shfl_xor_sync(0xffffffffu, a1, o);
            }
            if (lane == d) {
                outp[obase + l0 * C_ + d] = a0 * inv0;
                outp[obase + l1 * C_ + d] = a1 * inv1;
            }
        }
    }
}

// ---------------- generic SGEMM: C = A(MxK) * Bw(NxK)^T (+bias)(+gelu)(+res) ----------------
template <int ACT, bool RES, bool BIAS>
__global__ __launch_bounds__(256) void gemm_kernel(const float* __restrict__ A,
                                                   const float* __restrict__ Bw,
                                                   const float* __restrict__ bias,
                                                   const float* __restrict__ res,
                                                   float* __restrict__ Co,
                                                   int M, int N, int K)
{
    __shared__ float As[8][128];
    __shared__ float Bs[8][128];
    int tid = threadIdx.x;
    int tx = tid & 15, ty = tid >> 4;
    int bm = blockIdx.y * 128, bn = blockIdx.x * 128;
    int lr = tid >> 1;            // 0..127
    int lk = (tid & 1) * 4;       // 0 or 4
    const float* Aptr = A + (size_t)(bm + lr) * K + lk;
    bool bvalid = (bn + lr) < N;
    const float* Bptr = Bw + (size_t)(bn + lr) * K + lk;

    float c[8][8];
#pragma unroll
    for (int i = 0; i < 8; i++)
#pragma unroll
        for (int j = 0; j < 8; j++) c[i][j] = 0.f;

    for (int k0 = 0; k0 < K; k0 += 8) {
        float4 av = *(const float4*)(Aptr + k0);
        float4 bv = bvalid ? *(const float4*)(Bptr + k0) : make_float4(0.f, 0.f, 0.f, 0.f);
        __syncthreads();
        As[lk + 0][lr] = av.x; As[lk + 1][lr] = av.y; As[lk + 2][lr] = av.z; As[lk + 3][lr] = av.w;
        Bs[lk + 0][lr] = bv.x; Bs[lk + 1][lr] = bv.y; Bs[lk + 2][lr] = bv.z; Bs[lk + 3][lr] = bv.w;
        __syncthreads();
#pragma unroll
        for (int kk = 0; kk < 8; kk++) {
            float a[8], b[8];
#pragma unroll
            for (int i = 0; i < 8; i++) a[i] = As[kk][ty * 8 + i];
#pragma unroll
            for (int j = 0; j < 8; j++) b[j] = Bs[kk][tx * 8 + j];
#pragma unroll
            for (int i = 0; i < 8; i++)
#pragma unroll
                for (int j = 0; j < 8; j++) c[i][j] = fmaf(a[i], b[j], c[i][j]);
        }
    }

#pragma unroll
    for (int i = 0; i < 8; i++) {
        int row = bm + ty * 8 + i;
#pragma unroll
        for (int j = 0; j < 8; j++) {
            int col = bn + tx * 8 + j;
            if (col < N) {
                float v = c[i][j];
                if (BIAS) v += bias[col];
                if (ACT == 1) v = 0.5f * v * (1.f + erff(v * 0.70710678118654752f));
                if (RES) v += res[(size_t)row * N + col];
                Co[(size_t)row * N + col] = v;
            }
        }
    }
}

// ---------------- launch ----------------
extern "C" void kernel_launch(void* const* d_in, const int* in_sizes, int n_in,
                              void* d_out, int out_size)
{
    const float* x      = (const float*)d_in[0];
    const float* n1w    = (const float*)d_in[1];
    const float* n1b    = (const float*)d_in[2];
    const float* qkv_w  = (const float*)d_in[3];
    const float* proj_w = (const float*)d_in[4];
    const float* proj_b = (const float*)d_in[5];
    const float* n2w    = (const float*)d_in[6];
    const float* n2b    = (const float*)d_in[7];
    const float* fc1w   = (const float*)d_in[8];
    const float* fc1b   = (const float*)d_in[9];
    const float* fc2w   = (const float*)d_in[10];
    const float* fc2b   = (const float*)d_in[11];
    const float* ppw    = (const float*)d_in[12];
    const float* ppb    = (const float*)d_in[13];
    const float* pl1w   = (const float*)d_in[14];
    const float* pl1b   = (const float*)d_in[15];
    const float* pf1w   = (const float*)d_in[16];
    const float* pf1b   = (const float*)d_in[17];
    const float* pl2w   = (const float*)d_in[18];
    const float* pl2b   = (const float*)d_in[19];
    const float* pf2w   = (const float*)d_in[20];
    const float* pf2b   = (const float*)d_in[21];
    const float* pl3w   = (const float*)d_in[22];
    const float* pl3b   = (const float*)d_in[23];
    const float* pf3w   = (const float*)d_in[24];
    const float* pf3b   = (const float*)d_in[25];
    float* out = (float*)d_out;

    float *p_xn, *p_qkv, *p_att, *p_x2, *p_y, *p_h1, *p_pos;
    cudaGetSymbolAddress((void**)&p_xn,  g_xn);
    cudaGetSymbolAddress((void**)&p_qkv, g_qkv);
    cudaGetSymbolAddress((void**)&p_att, g_att);
    cudaGetSymbolAddress((void**)&p_x2,  g_x2);
    cudaGetSymbolAddress((void**)&p_y,   g_y);
    cudaGetSymbolAddress((void**)&p_h1,  g_h1);
    cudaGetSymbolAddress((void**)&p_pos, g_pos);

    const int ATTN_SMEM = (48 * 785 + NREL * 4) * 4;   // 197104 B
    cudaFuncSetAttribute(attn_kernel<0>, cudaFuncAttributeMaxDynamicSharedMemorySize, ATTN_SMEM);
    cudaFuncSetAttribute(attn_kernel<1>, cudaFuncAttributeMaxDynamicSharedMemorySize, ATTN_SMEM);

    // 1) LN1
    ln_kernel<<<MROWS / 8, 256>>>(x, n1w, n1b, p_xn);
    // 2) pos-bias MLP tables
    pos_kernel<<<dim3(12, 2), 256>>>(ppw, ppb, pl1w, pl1b, pf1w, pf1b,
                                     pl2w, pl2b, pf2w, pf2b, pl3w, pl3b,
                                     pf3w, pf3b, p_pos);
    // 3) QKV GEMM (no bias)
    {
        dim3 grid((3 * C_ + 127) / 128, MROWS / 128);
        gemm_kernel<0, false, false><<<grid, 256>>>(p_xn, qkv_w, nullptr, nullptr,
                                                    p_qkv, MROWS, 3 * C_, C_);
    }
    // 4) attention (both branches)
    attn_kernel<0><<<128, 512, ATTN_SMEM>>>(p_qkv, p_pos, p_att);
    attn_kernel<1><<<128, 512, ATTN_SMEM>>>(p_qkv, p_pos, p_att);
    // 5) proj + bias + residual(x) -> x2
    {
        dim3 grid((C_ + 127) / 128, MROWS / 128);
        gemm_kernel<0, true, true><<<grid, 256>>>(p_att, proj_w, proj_b, x,
                                                  p_x2, MROWS, C_, C_);
    }
    // 6) LN2
    ln_kernel<<<MROWS / 8, 256>>>(p_x2, n2w, n2b, p_y);
    // 7) fc1 + bias + gelu
    {
        dim3 grid((HID + 127) / 128, MROWS / 128);
        gemm_kernel<1, false, true><<<grid, 256>>>(p_y, fc1w, fc1b, nullptr,
                                                   p_h1, MROWS, HID, C_);
    }
    // 8) fc2 + bias + residual(x2) -> out
    {
        dim3 grid((C_ + 127) / 128, MROWS / 128);
        gemm_kernel<0, true, true><<<grid, 256>>>(p_h1, fc2w, fc2b, p_x2,
                                                  out, MROWS, C_, HID);
    }
}